// round 3
// baseline (speedup 1.0000x reference)
#include <cuda_runtime.h>

#define NSTAGES 12
#define NPAIRS  2048
#define NCOLS   4096
#define NROWS   4096
#define RPC     8       // rows per CTA
#define CHUNK   4       // rows resident in smem at once (64 KB)
#define NCHUNK  (RPC / CHUNK)
#define TPB     512

// Bank-conflict-free swizzle for all four exchange patterns (D = 1, 8, 64, 512).
__device__ __forceinline__ int swz(int a) {
    return a ^ ((a >> 5) & 7) ^ (((a >> 6) & 3) << 3);
}

__device__ __forceinline__ void rot(float2 cs, float& a, float& b) {
    float a2 = cs.x * a - cs.y * b;
    float b2 = cs.y * a + cs.x * b;
    a = a2;
    b = b2;
}

// Group K handles stages s = 3K..3K+2 (dist = D, 2D, 4D with D = 8^K)
// entirely in registers, for one CHUNK of rows. Angles are loaded raw and
// converted with MUFU sincos in-kernel (error ~1e-6 for these tiny angles).
template<int K>
__device__ __forceinline__ void do_group(float* sm, const float* __restrict__ gx,
                                         float* __restrict__ gy,
                                         const float* __restrict__ ang,
                                         int t, long cb) {
    const int D      = 1 << (3 * K);
    const int off    = t & (D - 1);
    const int blk    = t >> (3 * K);
    const int base_n = blk * 8 * D + off;
    const int base_p = blk * 4 * D + off;

    float2 cs[3][4];
    if (K == 0) {
        // base_p = 4t: the 4 angles per stage are contiguous -> float4 loads
#pragma unroll
        for (int u = 0; u < 3; u++) {
            float4 a = __ldg(reinterpret_cast<const float4*>(ang + u * NPAIRS) + t);
            __sincosf(a.x, &cs[u][0].y, &cs[u][0].x);
            __sincosf(a.y, &cs[u][1].y, &cs[u][1].x);
            __sincosf(a.z, &cs[u][2].y, &cs[u][2].x);
            __sincosf(a.w, &cs[u][3].y, &cs[u][3].x);
        }
    } else {
#pragma unroll
        for (int u = 0; u < 3; u++) {
#pragma unroll
            for (int m = 0; m < 4; m++) {
                float a = __ldg(ang + (3 * K + u) * NPAIRS + base_p + m * D);
                __sincosf(a, &cs[u][m].y, &cs[u][m].x);
            }
        }
    }

#pragma unroll
    for (int r = 0; r < CHUNK; r++) {
        float v[8];
        float* smr = sm + r * NCOLS;

        if (K == 0) {
            const float4* p =
                reinterpret_cast<const float4*>(gx + cb + (long)r * NCOLS + 8 * t);
            float4 f0 = __ldg(p);
            float4 f1 = __ldg(p + 1);
            v[0] = f0.x; v[1] = f0.y; v[2] = f0.z; v[3] = f0.w;
            v[4] = f1.x; v[5] = f1.y; v[6] = f1.z; v[7] = f1.w;
        } else {
#pragma unroll
            for (int j = 0; j < 8; j++)
                v[j] = smr[swz(base_n + D * j)];
        }

        // stage u=0 (dist = D): pairs (2m, 2m+1)
#pragma unroll
        for (int m = 0; m < 4; m++) rot(cs[0][m], v[2 * m], v[2 * m + 1]);

        // stage u=1 (dist = 2D): pairs (j, j+2), j in {0,1,4,5}
#pragma unroll
        for (int m = 0; m < 4; m++) {
            int j = ((m >> 1) << 2) | (m & 1);
            rot(cs[1][m], v[j], v[j + 2]);
        }

        // stage u=2 (dist = 4D): pairs (m, m+4)
#pragma unroll
        for (int m = 0; m < 4; m++) rot(cs[2][m], v[m], v[m + 4]);

        if (K == 3) {
            // n = t + 512*j: consecutive lanes -> consecutive addresses, coalesced
#pragma unroll
            for (int j = 0; j < 8; j++)
                gy[cb + (long)r * NCOLS + t + 512 * j] = v[j];
        } else {
#pragma unroll
            for (int j = 0; j < 8; j++)
                smr[swz(base_n + D * j)] = v[j];
        }
    }
}

__global__ void __launch_bounds__(TPB, 2)
butterfly_kernel(const float* __restrict__ x, const float* __restrict__ ang,
                 float* __restrict__ y) {
    extern __shared__ float sm[];   // CHUNK * NCOLS floats = 64 KB
    int t = threadIdx.x;
    long base = (long)blockIdx.x * RPC * NCOLS;

#pragma unroll
    for (int c = 0; c < NCHUNK; c++) {
        long cb = base + (long)c * CHUNK * NCOLS;
        do_group<0>(sm, x, y, ang, t, cb);   // global -> regs, stages 0-2, -> smem
        __syncthreads();
        do_group<1>(sm, x, y, ang, t, cb);   // smem -> regs, stages 3-5, -> smem
        __syncthreads();
        do_group<2>(sm, x, y, ang, t, cb);   // smem -> regs, stages 6-8, -> smem
        __syncthreads();
        do_group<3>(sm, x, y, ang, t, cb);   // smem -> regs, stages 9-11, -> global
        if (c + 1 < NCHUNK) __syncthreads(); // protect smem reuse by next chunk
    }
}

extern "C" void kernel_launch(void* const* d_in, const int* in_sizes, int n_in,
                              void* d_out, int out_size) {
    const float* x   = (const float*)d_in[0];
    const float* ang = (const float*)d_in[1];
    float* y         = (float*)d_out;

    (void)in_sizes; (void)n_in; (void)out_size;

    cudaFuncSetAttribute(butterfly_kernel,
                         cudaFuncAttributeMaxDynamicSharedMemorySize,
                         CHUNK * NCOLS * (int)sizeof(float));

    butterfly_kernel<<<NROWS / RPC, TPB, CHUNK * NCOLS * sizeof(float)>>>(x, ang, y);
}

// round 4
// speedup vs baseline: 1.3664x; 1.3664x over previous
#include <cuda_runtime.h>

#define NSTAGES 12
#define NPAIRS  2048
#define NCOLS   4096
#define NROWS   4096
#define RPC     4       // rows per CTA -> 64 KB smem -> 2 CTAs/SM
#define TPB     512

// Bank-conflict-free swizzle for all four exchange patterns (D = 1, 8, 64, 512).
__device__ __forceinline__ int swz(int a) {
    return a ^ ((a >> 5) & 7) ^ (((a >> 6) & 3) << 3);
}

// Polynomial sin/cos for |a| <~ 0.15 (angles are 0.02*N(0,1)).
// Returns c1 = cos(a)-1 (no cancellation) and s = sin(a).
// Truncation error < 5e-9. All FMA-pipe, zero MUFU.
__device__ __forceinline__ float2 cs_poly(float a) {
    float x2 = a * a;
    float c1 = x2 * fmaf(x2, (1.0f / 24.0f), -0.5f);
    float s  = a * fmaf(x2, fmaf(x2, (1.0f / 120.0f), (-1.0f / 6.0f)), 1.0f);
    return make_float2(c1, s);
}

// Rotation using c1 = c-1: 4 FFMA, mathematically = (c*v0 - s*v1, s*v0 + c*v1).
__device__ __forceinline__ void rot(float2 cs, float& a, float& b) {
    float ta = fmaf(cs.x, a, a);        // c*a
    float tb = fmaf(cs.x, b, b);        // c*b
    float y0 = fmaf(-cs.y, b, ta);
    float y1 = fmaf(cs.y, a, tb);
    a = y0;
    b = y1;
}

// Group K handles stages s = 3K..3K+2 (dist = D, 2D, 4D with D = 8^K)
// entirely in registers. Thread holds elements n = blk*8D + off + D*j, j=0..7.
// Angles loaded raw once per group, converted via FMA polynomial.
template<int K>
__device__ __forceinline__ void do_group(float* sm, const float* __restrict__ gx,
                                         float* __restrict__ gy,
                                         const float* __restrict__ ang,
                                         int t, long rowBase) {
    const int D      = 1 << (3 * K);
    const int off    = t & (D - 1);
    const int blk    = t >> (3 * K);
    const int base_n = blk * 8 * D + off;
    const int base_p = blk * 4 * D + off;

    float2 cs[3][4];
    if (K == 0) {
        // base_p = 4t: 4 contiguous angles per stage -> one float4 load each
#pragma unroll
        for (int u = 0; u < 3; u++) {
            float4 a = __ldg(reinterpret_cast<const float4*>(ang + u * NPAIRS) + t);
            cs[u][0] = cs_poly(a.x);
            cs[u][1] = cs_poly(a.y);
            cs[u][2] = cs_poly(a.z);
            cs[u][3] = cs_poly(a.w);
        }
    } else {
#pragma unroll
        for (int u = 0; u < 3; u++) {
#pragma unroll
            for (int m = 0; m < 4; m++) {
                cs[u][m] = cs_poly(__ldg(ang + (3 * K + u) * NPAIRS + base_p + m * D));
            }
        }
    }

    // Fully unrolled over rows: front-batched LDG/LDS/STG streams for high MLP.
#pragma unroll
    for (int r = 0; r < RPC; r++) {
        float v[8];
        float* smr = sm + r * NCOLS;

        if (K == 0) {
            const float4* p =
                reinterpret_cast<const float4*>(gx + rowBase + (long)r * NCOLS + 8 * t);
            float4 f0 = __ldg(p);
            float4 f1 = __ldg(p + 1);
            v[0] = f0.x; v[1] = f0.y; v[2] = f0.z; v[3] = f0.w;
            v[4] = f1.x; v[5] = f1.y; v[6] = f1.z; v[7] = f1.w;
        } else {
#pragma unroll
            for (int j = 0; j < 8; j++)
                v[j] = smr[swz(base_n + D * j)];
        }

        // stage u=0 (dist = D): pairs (2m, 2m+1)
#pragma unroll
        for (int m = 0; m < 4; m++) rot(cs[0][m], v[2 * m], v[2 * m + 1]);

        // stage u=1 (dist = 2D): pairs (j, j+2), j in {0,1,4,5}
#pragma unroll
        for (int m = 0; m < 4; m++) {
            int j = ((m >> 1) << 2) | (m & 1);
            rot(cs[1][m], v[j], v[j + 2]);
        }

        // stage u=2 (dist = 4D): pairs (m, m+4)
#pragma unroll
        for (int m = 0; m < 4; m++) rot(cs[2][m], v[m], v[m + 4]);

        if (K == 3) {
            // n = t + 512*j: consecutive lanes -> consecutive addresses, coalesced
#pragma unroll
            for (int j = 0; j < 8; j++)
                gy[rowBase + (long)r * NCOLS + t + 512 * j] = v[j];
        } else {
#pragma unroll
            for (int j = 0; j < 8; j++)
                smr[swz(base_n + D * j)] = v[j];
        }
    }
}

__global__ void __launch_bounds__(TPB, 2)
butterfly_kernel(const float* __restrict__ x, const float* __restrict__ ang,
                 float* __restrict__ y) {
    extern __shared__ float sm[];   // RPC * NCOLS floats = 64 KB
    int t = threadIdx.x;
    long rowBase = (long)blockIdx.x * RPC * NCOLS;

    do_group<0>(sm, x, y, ang, t, rowBase);   // global -> regs, stages 0-2, -> smem
    __syncthreads();
    do_group<1>(sm, x, y, ang, t, rowBase);   // smem -> regs, stages 3-5, -> smem
    __syncthreads();
    do_group<2>(sm, x, y, ang, t, rowBase);   // smem -> regs, stages 6-8, -> smem
    __syncthreads();
    do_group<3>(sm, x, y, ang, t, rowBase);   // smem -> regs, stages 9-11, -> global
}

extern "C" void kernel_launch(void* const* d_in, const int* in_sizes, int n_in,
                              void* d_out, int out_size) {
    const float* x   = (const float*)d_in[0];
    const float* ang = (const float*)d_in[1];
    float* y         = (float*)d_out;

    (void)in_sizes; (void)n_in; (void)out_size;

    cudaFuncSetAttribute(butterfly_kernel,
                         cudaFuncAttributeMaxDynamicSharedMemorySize,
                         RPC * NCOLS * (int)sizeof(float));

    butterfly_kernel<<<NROWS / RPC, TPB, RPC * NCOLS * sizeof(float)>>>(x, ang, y);
}